// round 2
// baseline (speedup 1.0000x reference)
#include <cuda_runtime.h>

#define N_NODES_C 50000
#define D_FEAT 64
#define D_OUT 64
#define N_REL 8
#define N_BASES 4
#define K_DIM (D_FEAT * N_BASES)   /* 256 */
#define NODE_TILE 128
#define KC 64                      /* k-chunk */
#define TBLOCK 256

// Scratch: transformed node features y[n][o]  (12.8 MB)
__device__ float g_y[(size_t)N_NODES_C * D_OUT];

#define FMA2(acc, a, b) \
    asm("fma.rn.f32x2 %0, %1, %2, %0;" : "+l"(acc) : "l"(a), "l"(b))

__device__ __forceinline__ unsigned long long pack2(float v) {
    unsigned long long r;
    unsigned u = __float_as_uint(v);
    asm("mov.b64 %0, {%1, %1};" : "=l"(r) : "r"(u));
    return r;
}

// ---------------------------------------------------------------------------
// Fused transform: y = (x @_r w_rel) @_{i,b} w_bases
// smem: wb_s [256 k][64 o] (64KB), z_s [64 kc][128 n] (32KB), wrel_s [8][4]
// Per k-chunk: Phase A computes z chunk, Phase B accumulates 8n x 4o per thread
// with fma.rn.f32x2 (f32x2 pairs over the node dimension).
// ---------------------------------------------------------------------------
extern "C" __global__ void __launch_bounds__(TBLOCK, 2)
rgcn_transform(const float* __restrict__ x,
               const float* __restrict__ w_bases,
               const float* __restrict__ w_rel,
               int n_nodes, int n_tiles)
{
    extern __shared__ float smem[];
    float* wb_s   = smem;                         // 16384 floats
    float* z_s    = smem + K_DIM * D_OUT;         // 8192 floats
    float* wrel_s = z_s + KC * NODE_TILE;         // 32 floats

    const int t = threadIdx.x;

    if (t < N_REL * N_BASES) wrel_s[t] = w_rel[t];
    // wb_s[(i*4+b)*64 + o] = w_bases[b][i][o]
    for (int idx = t; idx < K_DIM * D_OUT; idx += TBLOCK) {
        int k = idx >> 6, o = idx & 63;
        int b = k & 3,   i = k >> 2;
        wb_s[idx] = w_bases[(b * D_FEAT + i) * D_OUT + o];
    }
    __syncthreads();

    const int ngroup = t & 15;       // 16 node groups of 8 nodes
    const int ogroup = t >> 4;       // 16 out groups of 4 outs
    // warp = 16 ngroups x 2 ogroups -> wb LDS is a 2-address broadcast

    for (int tile = blockIdx.x; tile < n_tiles; tile += gridDim.x) {
        const int node0 = tile * NODE_TILE;

        unsigned long long acc[4][4];   // [node-pair j][out o], f32x2 over nodes
        #pragma unroll
        for (int j = 0; j < 4; j++)
            #pragma unroll
            for (int o = 0; o < 4; o++) acc[j][o] = 0ull;

        #pragma unroll
        for (int c = 0; c < K_DIM / KC; c++) {   // 4 chunks
            __syncthreads();   // previous chunk's readers done with z_s

            // ---- Phase A: z chunk (i in [c*16, c*16+16)) ----------------
            #pragma unroll
            for (int it = 0; it < (NODE_TILE * 16) / TBLOCK; it++) {  // 8
                int p = t + it * TBLOCK;          // 0..2047
                int n  = p & (NODE_TILE - 1);
                int ii = p >> 7;                  // 0..15
                int node = node0 + n;
                if (node < n_nodes) {
                    const float4* xr = (const float4*)
                        (x + ((size_t)node * D_FEAT + (c * 16 + ii)) * N_REL);
                    float4 x0 = xr[0];
                    float4 x1 = xr[1];
                    #pragma unroll
                    for (int b = 0; b < 4; b++) {
                        float z = x0.x * wrel_s[0*4+b] + x0.y * wrel_s[1*4+b]
                                + x0.z * wrel_s[2*4+b] + x0.w * wrel_s[3*4+b]
                                + x1.x * wrel_s[4*4+b] + x1.y * wrel_s[5*4+b]
                                + x1.z * wrel_s[6*4+b] + x1.w * wrel_s[7*4+b];
                        z_s[(ii * 4 + b) * NODE_TILE + n] = z;
                    }
                } else {
                    #pragma unroll
                    for (int b = 0; b < 4; b++)
                        z_s[(ii * 4 + b) * NODE_TILE + n] = 0.f;
                }
            }
            __syncthreads();

            // ---- Phase B: acc += z_chunk @ wb_chunk ---------------------
            const float* wb_c = wb_s + (c * KC) * D_OUT;
            #pragma unroll 8
            for (int kk = 0; kk < KC; kk++) {
                const ulonglong2* zp = (const ulonglong2*)
                    (z_s + kk * NODE_TILE + ngroup * 8);
                ulonglong2 za = zp[0];   // node pairs (0,1),(2,3)
                ulonglong2 zb = zp[1];   // node pairs (4,5),(6,7)
                float4 wv = *(const float4*)(wb_c + kk * D_OUT + ogroup * 4);
                unsigned long long w0 = pack2(wv.x);
                unsigned long long w1 = pack2(wv.y);
                unsigned long long w2 = pack2(wv.z);
                unsigned long long w3 = pack2(wv.w);
                FMA2(acc[0][0], za.x, w0); FMA2(acc[0][1], za.x, w1);
                FMA2(acc[0][2], za.x, w2); FMA2(acc[0][3], za.x, w3);
                FMA2(acc[1][0], za.y, w0); FMA2(acc[1][1], za.y, w1);
                FMA2(acc[1][2], za.y, w2); FMA2(acc[1][3], za.y, w3);
                FMA2(acc[2][0], zb.x, w0); FMA2(acc[2][1], zb.x, w1);
                FMA2(acc[2][2], zb.x, w2); FMA2(acc[2][3], zb.x, w3);
                FMA2(acc[3][0], zb.y, w0); FMA2(acc[3][1], zb.y, w1);
                FMA2(acc[3][2], zb.y, w2); FMA2(acc[3][3], zb.y, w3);
            }
        }

        // ---- store y ---------------------------------------------------
        #pragma unroll
        for (int j = 0; j < 4; j++) {
            int n0 = node0 + ngroup * 8 + 2 * j;
            if (n0 < n_nodes) {
                float4 v;
                v.x = __uint_as_float((unsigned)acc[j][0]);
                v.y = __uint_as_float((unsigned)acc[j][1]);
                v.z = __uint_as_float((unsigned)acc[j][2]);
                v.w = __uint_as_float((unsigned)acc[j][3]);
                *(float4*)(g_y + (size_t)n0 * D_OUT + ogroup * 4) = v;
            }
            if (n0 + 1 < n_nodes) {
                float4 v;
                v.x = __uint_as_float((unsigned)(acc[j][0] >> 32));
                v.y = __uint_as_float((unsigned)(acc[j][1] >> 32));
                v.z = __uint_as_float((unsigned)(acc[j][2] >> 32));
                v.w = __uint_as_float((unsigned)(acc[j][3] >> 32));
                *(float4*)(g_y + (size_t)(n0 + 1) * D_OUT + ogroup * 4) = v;
            }
        }
        __syncthreads();   // protect z_s before next tile's Phase A
    }
}

// ---------------------------------------------------------------------------
// Edge scatter: out[dst] += w_e * y[src]
// 4 threads per edge, each does 4x (LDG.128 + RED.128) -> MLP=4 per thread.
// ---------------------------------------------------------------------------
extern "C" __global__ void rgcn_scatter(const int*   __restrict__ esrc,
                                        const int*   __restrict__ edst,
                                        const float* __restrict__ ew,
                                        float*       __restrict__ out,
                                        int n_edges)
{
    int idx = blockIdx.x * blockDim.x + threadIdx.x;
    if (idx >= n_edges * 4) return;
    int e    = idx >> 2;
    int part = idx & 3;           // 16 floats each
    int s = __ldg(esrc + e);
    int d = __ldg(edst + e);
    float w = __ldg(ew + e);
    const float4* ys = (const float4*)(g_y + (size_t)s * D_OUT) + part * 4;
    float4 v0 = ys[0];
    float4 v1 = ys[1];
    float4 v2 = ys[2];
    float4 v3 = ys[3];
    float* p = out + (size_t)d * D_OUT + part * 16;
    asm volatile("red.global.add.v4.f32 [%0], {%1, %2, %3, %4};"
                 :: "l"(p),      "f"(v0.x*w), "f"(v0.y*w), "f"(v0.z*w), "f"(v0.w*w) : "memory");
    asm volatile("red.global.add.v4.f32 [%0], {%1, %2, %3, %4};"
                 :: "l"(p + 4),  "f"(v1.x*w), "f"(v1.y*w), "f"(v1.z*w), "f"(v1.w*w) : "memory");
    asm volatile("red.global.add.v4.f32 [%0], {%1, %2, %3, %4};"
                 :: "l"(p + 8),  "f"(v2.x*w), "f"(v2.y*w), "f"(v2.z*w), "f"(v2.w*w) : "memory");
    asm volatile("red.global.add.v4.f32 [%0], {%1, %2, %3, %4};"
                 :: "l"(p + 12), "f"(v3.x*w), "f"(v3.y*w), "f"(v3.z*w), "f"(v3.w*w) : "memory");
}

// ---------------------------------------------------------------------------
extern "C" void kernel_launch(void* const* d_in, const int* in_sizes, int n_in,
                              void* d_out, int out_size)
{
    const float* x    = (const float*)d_in[0];
    const int*   esrc = (const int*)  d_in[1];
    const int*   edst = (const int*)  d_in[2];
    const float* ew   = (const float*)d_in[3];
    const float* wb   = (const float*)d_in[4];
    const float* wrel = (const float*)d_in[5];
    float* out = (float*)d_out;

    const int n_nodes = in_sizes[0] / (D_FEAT * N_REL);
    const int n_edges = in_sizes[1];
    const int n_tiles = (n_nodes + NODE_TILE - 1) / NODE_TILE;

    const int smem_bytes =
        (K_DIM * D_OUT + KC * NODE_TILE + N_REL * N_BASES) * sizeof(float);
    static int configured = 0;
    cudaFuncSetAttribute(rgcn_transform,
                         cudaFuncAttributeMaxDynamicSharedMemorySize, smem_bytes);
    (void)configured;

    cudaMemsetAsync(d_out, 0, (size_t)out_size * sizeof(float), 0);

    rgcn_transform<<<296, TBLOCK, smem_bytes>>>(x, wb, wrel, n_nodes, n_tiles);

    int total = n_edges * 4;
    int blocks = (total + TBLOCK - 1) / TBLOCK;
    rgcn_scatter<<<blocks, TBLOCK>>>(esrc, edst, ew, out, n_edges);
}

// round 3
// speedup vs baseline: 1.3494x; 1.3494x over previous
#include <cuda_runtime.h>

#define N_NODES_C 50000
#define D_FEAT 64
#define D_OUT 64
#define N_REL 8
#define N_BASES 4
#define K_DIM 256
#define NODE_TILE 64
#define KC 64           /* k per chunk = 16 i * 4 b */
#define NCHUNK 4
#define TBLOCK 256

typedef unsigned long long ull;

// Scratch: transformed node features y[n][o]  (12.8 MB)
__device__ float g_y[(size_t)N_NODES_C * D_OUT];

#define FMA2(acc, a, b) \
    asm("fma.rn.f32x2 %0, %1, %2, %0;" : "+l"(acc) : "l"(a), "l"(b))

__device__ __forceinline__ ull pack2(float v) {
    ull r; unsigned u = __float_as_uint(v);
    asm("mov.b64 %0, {%1, %1};" : "=l"(r) : "r"(u));
    return r;
}
__device__ __forceinline__ ull pack2pair(float lo, float hi) {
    ull r;
    asm("mov.b64 %0, {%1, %2};" : "=l"(r)
        : "r"(__float_as_uint(lo)), "r"(__float_as_uint(hi)));
    return r;
}
__device__ __forceinline__ float2 unpack2(ull v) {
    unsigned lo, hi;
    asm("mov.b64 {%0, %1}, %2;" : "=r"(lo), "=r"(hi) : "l"(v));
    return make_float2(__uint_as_float(lo), __uint_as_float(hi));
}

// ---------------------------------------------------------------------------
// Fused transform: y = (x @_r w_rel) @_{i,b} w_bases
// smem: wb_s [256 k][64 o], z_s [64 k][64 n] (xor-swizzled 16B groups),
//       wrel2_s [8 r][2 b-pair] as f32x2
// ---------------------------------------------------------------------------
extern "C" __global__ void __launch_bounds__(TBLOCK, 2)
rgcn_transform(const float* __restrict__ x,
               const float* __restrict__ w_bases,
               const float* __restrict__ w_rel,
               int n_nodes, int n_tiles)
{
    extern __shared__ float smem[];
    float* wb_s  = smem;                          // 16384 floats
    float* z_s   = smem + K_DIM * D_OUT;          // 4096 floats
    ull*  wrel2_s = (ull*)(z_s + KC * NODE_TILE); // 16 ulls

    const int t = threadIdx.x;

    if (t < N_REL * 2) {
        int r = t >> 1, bp = t & 1;
        wrel2_s[r * 2 + bp] = pack2pair(w_rel[r * 4 + 2 * bp],
                                        w_rel[r * 4 + 2 * bp + 1]);
    }
    // wb_s[(i*4+b)*64 + o] = w_bases[b][i][o]
    for (int idx = t; idx < K_DIM * D_OUT; idx += TBLOCK) {
        int k = idx >> 6, o = idx & 63;
        int b = k & 3,   i = k >> 2;
        wb_s[idx] = w_bases[(b * D_FEAT + i) * D_OUT + o];
    }

    const int og = t >> 4;   // 16 out groups of 4 outs
    const int ng = t & 15;   // 16 node groups of 4 nodes

    for (int tile = blockIdx.x; tile < n_tiles; tile += gridDim.x) {
        const int node0 = tile * NODE_TILE;

        ull acc[4][2];   // [node j][out-pair], f32x2 over outs
        #pragma unroll
        for (int j = 0; j < 4; j++) { acc[j][0] = 0ull; acc[j][1] = 0ull; }

        #pragma unroll
        for (int c = 0; c < NCHUNK; c++) {
            __syncthreads();   // prev chunk readers done / init done

            // ---- Phase A: z chunk. lanes: ii fast (coalesced-ish x) -----
            #pragma unroll
            for (int it = 0; it < (NODE_TILE * 16) / TBLOCK; it++) {  // 4
                int p  = t + it * TBLOCK;
                int ii = p & 15;          // i within chunk
                int n  = p >> 4;          // node within tile
                int node = node0 + n;
                ull zp0 = 0ull, zp1 = 0ull;   // b-pairs (0,1),(2,3)
                if (node < n_nodes) {
                    const float4* xr = (const float4*)
                        (x + ((size_t)node * D_FEAT + (c * 16 + ii)) * N_REL);
                    float4 x0 = xr[0];
                    float4 x1 = xr[1];
                    ull xp;
                    xp = pack2(x0.x); FMA2(zp0, xp, wrel2_s[0]);  FMA2(zp1, xp, wrel2_s[1]);
                    xp = pack2(x0.y); FMA2(zp0, xp, wrel2_s[2]);  FMA2(zp1, xp, wrel2_s[3]);
                    xp = pack2(x0.z); FMA2(zp0, xp, wrel2_s[4]);  FMA2(zp1, xp, wrel2_s[5]);
                    xp = pack2(x0.w); FMA2(zp0, xp, wrel2_s[6]);  FMA2(zp1, xp, wrel2_s[7]);
                    xp = pack2(x1.x); FMA2(zp0, xp, wrel2_s[8]);  FMA2(zp1, xp, wrel2_s[9]);
                    xp = pack2(x1.y); FMA2(zp0, xp, wrel2_s[10]); FMA2(zp1, xp, wrel2_s[11]);
                    xp = pack2(x1.z); FMA2(zp0, xp, wrel2_s[12]); FMA2(zp1, xp, wrel2_s[13]);
                    xp = pack2(x1.w); FMA2(zp0, xp, wrel2_s[14]); FMA2(zp1, xp, wrel2_s[15]);
                }
                float2 zlo = unpack2(zp0);   // b0, b1
                float2 zhi = unpack2(zp1);   // b2, b3
                // swizzled store: group slot = (n>>2) ^ ii  (2-way conflicts)
                int spos = (((n >> 2) ^ ii) << 2) + (n & 3);
                float* zb = z_s + (ii * 4) * NODE_TILE + spos;
                zb[0 * NODE_TILE] = zlo.x;
                zb[1 * NODE_TILE] = zlo.y;
                zb[2 * NODE_TILE] = zhi.x;
                zb[3 * NODE_TILE] = zhi.y;
            }
            __syncthreads();

            // ---- Phase B: acc += z_chunk @ wb_chunk ---------------------
            const float* wb_c = wb_s + (c * KC) * D_OUT + og * 4;
            #pragma unroll 8
            for (int k = 0; k < KC; k++) {
                int slot = ng ^ (k >> 2);
                float4 z4 = *(const float4*)(z_s + k * NODE_TILE + slot * 4);
                ulonglong2 w2 = *(const ulonglong2*)(wb_c + k * D_OUT);
                FMA2(acc[0][0], pack2(z4.x), w2.x);
                FMA2(acc[0][1], pack2(z4.x), w2.y);
                FMA2(acc[1][0], pack2(z4.y), w2.x);
                FMA2(acc[1][1], pack2(z4.y), w2.y);
                FMA2(acc[2][0], pack2(z4.z), w2.x);
                FMA2(acc[2][1], pack2(z4.z), w2.y);
                FMA2(acc[3][0], pack2(z4.w), w2.x);
                FMA2(acc[3][1], pack2(z4.w), w2.y);
            }
        }

        // ---- store y ---------------------------------------------------
        #pragma unroll
        for (int j = 0; j < 4; j++) {
            int node = node0 + ng * 4 + j;
            if (node < n_nodes) {
                float2 a = unpack2(acc[j][0]);
                float2 b = unpack2(acc[j][1]);
                *(float4*)(g_y + (size_t)node * D_OUT + og * 4) =
                    make_float4(a.x, a.y, b.x, b.y);
            }
        }
        __syncthreads();   // protect z_s before next tile's Phase A
    }
}

// ---------------------------------------------------------------------------
// Edge scatter: out[dst] += w_e * y[src]   (round-1 config: 16 thr/edge)
// ---------------------------------------------------------------------------
extern "C" __global__ void rgcn_scatter(const int*   __restrict__ esrc,
                                        const int*   __restrict__ edst,
                                        const float* __restrict__ ew,
                                        float*       __restrict__ out,
                                        int n_edges)
{
    int idx = blockIdx.x * blockDim.x + threadIdx.x;
    if (idx >= n_edges * 16) return;
    int e    = idx >> 4;
    int part = idx & 15;
    int s = esrc[e];
    int d = edst[e];
    float w = ew[e];
    float4 v = ((const float4*)(g_y + (size_t)s * D_OUT))[part];
    float* p = out + (size_t)d * D_OUT + part * 4;
    asm volatile("red.global.add.v4.f32 [%0], {%1, %2, %3, %4};"
                 :: "l"(p), "f"(v.x * w), "f"(v.y * w), "f"(v.z * w), "f"(v.w * w)
                 : "memory");
}

// ---------------------------------------------------------------------------
extern "C" void kernel_launch(void* const* d_in, const int* in_sizes, int n_in,
                              void* d_out, int out_size)
{
    const float* x    = (const float*)d_in[0];
    const int*   esrc = (const int*)  d_in[1];
    const int*   edst = (const int*)  d_in[2];
    const float* ew   = (const float*)d_in[3];
    const float* wb   = (const float*)d_in[4];
    const float* wrel = (const float*)d_in[5];
    float* out = (float*)d_out;

    const int n_nodes = in_sizes[0] / (D_FEAT * N_REL);
    const int n_edges = in_sizes[1];
    const int n_tiles = (n_nodes + NODE_TILE - 1) / NODE_TILE;

    const int smem_bytes = (K_DIM * D_OUT + KC * NODE_TILE) * sizeof(float)
                         + N_REL * 2 * sizeof(ull);
    cudaFuncSetAttribute(rgcn_transform,
                         cudaFuncAttributeMaxDynamicSharedMemorySize, smem_bytes);

    cudaMemsetAsync(d_out, 0, (size_t)out_size * sizeof(float), 0);

    rgcn_transform<<<296, TBLOCK, smem_bytes>>>(x, wb, wrel, n_nodes, n_tiles);

    int total = n_edges * 16;
    int blocks = (total + TBLOCK - 1) / TBLOCK;
    rgcn_scatter<<<blocks, TBLOCK>>>(esrc, edst, ew, out, n_edges);
}